// round 11
// baseline (speedup 1.0000x reference)
#include <cuda_runtime.h>
#include <cuda_bf16.h>
#include <cstdint>

// Problem: T=256, B=64, E=512, H=512, HD=256, L=2, K=7
#define NEG_ -10000.0f

// packed f32x2 helpers (sm_103a)
#define FMA2(d, a, b) asm("fma.rn.f32x2 %0, %1, %2, %0;" : "+l"(d) : "l"(a), "l"(b))
#define PACK2(out, v) asm("mov.b64 %0, {%1, %1};" : "=l"(out) : "r"(__float_as_uint(v)))
#define UNPK2(lo, hi, in) asm("mov.b64 {%0, %1}, %2;" : "=r"(lo), "=r"(hi) : "l"(in))

// ---------------- device scratch (no cudaMalloc allowed) ----------------
__device__ float g_x [16384*512];   // embedded input (layer0 GEMM A)
__device__ float g_y0[16384*512];   // layer0 hidden output [m][dir*256+hd]
__device__ float g_y1[16384*512];   // layer1 hidden output
__device__ float g_xg[16384*2048];  // input-gate preacts [m][dir*1024 + gate*256 + hd]
__device__ float g_feats[16384*7];

// LSTM smem layout (floats):
//   W_s   : 128 rows x 276   (row = gate*32+hd; K-half0 cols 0..127, half1 at 144..271)
//   h_loc : 16 rows x 276    (2 parity x 8 batches)
//   xg_s  : 2 x 1056         (double-buffered cp.async target, stride 33 per (b,g))
#define GSTR  276
#define KSOFF 144
#define W_FLOATS   (128*GSTR)
#define H_FLOATS   (16*GSTR)
#define XG_OFF     (W_FLOATS + H_FLOATS)
#define XG_STRIDE  33
#define XG_BUF     (32*XG_STRIDE)     /* 1056 */
#define LSTM_SMEM_BYTES ((XG_OFF + 2*XG_BUF) * 4)   /* 167424 */
#define VIT_SMEM_BYTES  (256*64*4)                  /* 65536  */

// ============================================================
// 1) Embedding gather
// ============================================================
__global__ void __launch_bounds__(256) embed_kernel(const int* __restrict__ sent,
                                                    const float* __restrict__ emb)
{
    int gw   = (blockIdx.x * 256 + threadIdx.x) >> 5;
    int lane = threadIdx.x & 31;
    int nw   = gridDim.x * 8;
    for (int row = gw; row < 16384; row += nw) {
        int tok = sent[row];
        const float4* s = (const float4*)(emb + (size_t)tok * 512);
        float4*       d = (float4*)(g_x + (size_t)row * 512);
        #pragma unroll
        for (int i = 0; i < 4; i++) d[lane + i * 32] = s[lane + i * 32];
    }
}

// ============================================================
// 2) GEMM: g_xg[m][n] = A[m][:] . W[n][:] + b1[n] + b2[n]
//    128x128 tile, BK=8, 256 threads, 8x8 microtile via f32x2 FMA,
//    double-buffered smem (one __syncthreads per k-tile).
// ============================================================
__global__ void __launch_bounds__(256, 2)
gemm_kernel(const float* __restrict__ W, const float* __restrict__ b1,
            const float* __restrict__ b2, int layer)
{
    const float* A = layer ? g_y0 : g_x;
    __shared__ __align__(16) float As[2][8][132];
    __shared__ __align__(16) float Bs[2][8][132];

    int tid  = threadIdx.x;
    int m0   = blockIdx.y * 128;
    int n0   = blockIdx.x * 128;
    int lrow = tid >> 1;            // 0..127
    int kc   = (tid & 1) * 4;       // 0 or 4
    const float* Ap = A + (size_t)(m0 + lrow) * 512 + kc;
    const float* Wp = W + (size_t)(n0 + lrow) * 512 + kc;
    int tr = tid >> 4;              // 0..15
    int tc = tid & 15;              // 0..15

    unsigned long long acc2[8][4];
    #pragma unroll
    for (int i = 0; i < 8; i++)
        #pragma unroll
        for (int j = 0; j < 4; j++) acc2[i][j] = 0ull;

    {
        float4 pa = *(const float4*)Ap;
        float4 pb = *(const float4*)Wp;
        As[0][kc + 0][lrow] = pa.x; As[0][kc + 1][lrow] = pa.y;
        As[0][kc + 2][lrow] = pa.z; As[0][kc + 3][lrow] = pa.w;
        Bs[0][kc + 0][lrow] = pb.x; Bs[0][kc + 1][lrow] = pb.y;
        Bs[0][kc + 2][lrow] = pb.z; Bs[0][kc + 3][lrow] = pb.w;
    }
    __syncthreads();

    for (int kt = 0; kt < 64; kt++) {
        int cur = kt & 1;
        float4 na, nb;
        if (kt < 63) {
            na = *(const float4*)(Ap + (kt + 1) * 8);
            nb = *(const float4*)(Wp + (kt + 1) * 8);
        }
        #pragma unroll
        for (int kk = 0; kk < 8; kk++) {
            float4 alo = *(const float4*)&As[cur][kk][tr * 4];
            float4 ahi = *(const float4*)&As[cur][kk][64 + tr * 4];
            ulonglong2 bl = *(const ulonglong2*)&Bs[cur][kk][tc * 4];
            ulonglong2 bh = *(const ulonglong2*)&Bs[cur][kk][64 + tc * 4];
            float av[8] = {alo.x, alo.y, alo.z, alo.w, ahi.x, ahi.y, ahi.z, ahi.w};
            #pragma unroll
            for (int i = 0; i < 8; i++) {
                unsigned long long a2;
                PACK2(a2, av[i]);
                FMA2(acc2[i][0], a2, bl.x);
                FMA2(acc2[i][1], a2, bl.y);
                FMA2(acc2[i][2], a2, bh.x);
                FMA2(acc2[i][3], a2, bh.y);
            }
        }
        if (kt < 63) {
            int nxt = cur ^ 1;
            As[nxt][kc + 0][lrow] = na.x; As[nxt][kc + 1][lrow] = na.y;
            As[nxt][kc + 2][lrow] = na.z; As[nxt][kc + 3][lrow] = na.w;
            Bs[nxt][kc + 0][lrow] = nb.x; Bs[nxt][kc + 1][lrow] = nb.y;
            Bs[nxt][kc + 2][lrow] = nb.z; Bs[nxt][kc + 3][lrow] = nb.w;
            __syncthreads();
        }
    }

    #pragma unroll
    for (int i = 0; i < 8; i++) {
        int r = m0 + ((i < 4) ? (tr * 4 + i) : (64 + tr * 4 + i - 4));
        #pragma unroll
        for (int jh = 0; jh < 2; jh++) {
            int cb = n0 + jh * 64 + tc * 4;
            unsigned int u0, u1, u2, u3;
            UNPK2(u0, u1, acc2[i][jh * 2 + 0]);
            UNPK2(u2, u3, acc2[i][jh * 2 + 1]);
            float4 o;
            o.x = __uint_as_float(u0) + b1[cb + 0] + b2[cb + 0];
            o.y = __uint_as_float(u1) + b1[cb + 1] + b2[cb + 1];
            o.z = __uint_as_float(u2) + b1[cb + 2] + b2[cb + 2];
            o.w = __uint_as_float(u3) + b1[cb + 3] + b2[cb + 3];
            *(float4*)(g_xg + (size_t)r * 2048 + cb) = o;
        }
    }
}

// ============================================================
// 3) LSTM recurrence (one layer, both dirs).
//    128 CTAs = 16 clusters of 8; cluster = (dir, 8-batch chunk);
//    CTA rank r owns hd in [r*32, r*32+32).
//    512 threads: thread = (hd 0..31, b 0..7, ks 0..1) computes the
//    4 gate dots for ONE (hd, batch) over half of K; shfl.bfly(1)
//    completes K. xg preacts double-buffer prefetched via cp.async.
//    h exchanged via DSMEM (4 remote stores/thread) + barrier.cluster.
// ============================================================
__device__ __forceinline__ float sigf(float x) { return 1.0f / (1.0f + __expf(-x)); }

__global__ void __cluster_dims__(8, 1, 1) __launch_bounds__(512, 1)
lstm_kernel(const float* __restrict__ w_hh,   // layer base: [2][1024][256]
            const float* __restrict__ h0,     // [4][64][256]
            const float* __restrict__ c0,
            int layer)
{
    extern __shared__ float smem[];
    float* W_s   = smem;
    float* h_loc = smem + W_FLOATS;
    float* xg_s  = smem + XG_OFF;          // [2][XG_BUF]

    float* y = layer ? g_y1 : g_y0;

    int bx  = blockIdx.x;
    int cid = bx >> 3;                   // 0..15
    int r   = bx & 7;                    // hd-chunk rank
    int dir = cid & 1;
    int bc  = cid >> 1;                  // batch chunk 0..7
    int tid = threadIdx.x;
    int hd  = tid >> 4;                  // 0..31
    int b   = (tid >> 1) & 7;            // 0..7
    int ks  = tid & 1;                   // K-half
    int hd_g = r * 32 + hd;
    int b_g  = bc * 8 + b;

    // ---- load W_hh slice into split-row layout ----
    const float* Wd = w_hh + (size_t)dir * 1024 * 256;
    for (int i = tid; i < 128 * 64; i += 512) {
        int row = i >> 6, q = i & 63;
        int grow = (row >> 5) * 256 + r * 32 + (row & 31);
        float4 v = *(const float4*)(Wd + (size_t)grow * 256 + q * 4);
        int col = (q < 32) ? q * 4 : KSOFF + (q - 32) * 4;
        *(float4*)(W_s + row * GSTR + col) = v;
    }
    // ---- initial h (parity 0) ----
    const float* h0d = h0 + ((size_t)(2 * layer + dir) * 64 + bc * 8) * 256;
    {
        int i = tid;
        if (i < 512) {
            int row = i >> 6, q = i & 63;
            float4 v = *(const float4*)(h0d + row * 256 + q * 4);
            int col = (q < 32) ? q * 4 : KSOFF + (q - 32) * 4;
            *(float4*)(h_loc + row * GSTR + col) = v;
        }
    }
    float c = c0[((size_t)(2 * layer + dir) * 64 + b_g) * 256 + hd_g];

    // shared-address bases for cp.async
    uint32_t xg_sm_base = (uint32_t)__cvta_generic_to_shared(xg_s);

    // cp.async task: 2 tasks/thread, j in {tid, tid+512}: b=j>>7, g=(j>>5)&3, hd=j&31
    // gmem: (t*64 + bc*8 + b)*2048 + dir*1024 + g*256 + r*32 + hd   (coalesced 128B runs)
    // smem: buf + (b*4+g)*33 + hd
    int j0 = tid, j1 = tid + 512;
    int pb0 = j0 >> 7, pg0 = (j0 >> 5) & 3, ph0 = j0 & 31;
    int pb1 = j1 >> 7, pg1 = (j1 >> 5) & 3, ph1 = j1 & 31;
    const float* xsrc0 = g_xg + ((size_t)(bc * 8 + pb0)) * 2048 + (size_t)dir * 1024 + pg0 * 256 + r * 32 + ph0;
    const float* xsrc1 = g_xg + ((size_t)(bc * 8 + pb1)) * 2048 + (size_t)dir * 1024 + pg1 * 256 + r * 32 + ph1;
    uint32_t xdst0 = ((pb0 * 4 + pg0) * XG_STRIDE + ph0) * 4;
    uint32_t xdst1 = ((pb1 * 4 + pg1) * XG_STRIDE + ph1) * 4;

    // prefetch step 0
    {
        int t0 = dir ? 255 : 0;
        size_t toff = (size_t)t0 * 64 * 2048;
        uint32_t dbase = xg_sm_base;   // buffer 0
        asm volatile("cp.async.ca.shared.global [%0], [%1], 4;" ::
                     "r"(dbase + xdst0), "l"(xsrc0 + toff));
        asm volatile("cp.async.ca.shared.global [%0], [%1], 4;" ::
                     "r"(dbase + xdst1), "l"(xsrc1 + toff));
        asm volatile("cp.async.commit_group;");
    }
    __syncthreads();

    // precompute DSMEM push addresses: ks=0 -> ranks 0..3, ks=1 -> ranks 4..7
    uint32_t h_base = (uint32_t)__cvta_generic_to_shared(h_loc);
    int col_hd = (hd_g < 128) ? hd_g : KSOFF + (hd_g - 128);
    uint32_t dst0 = h_base + (uint32_t)((b * GSTR + col_hd) * 4);
    uint32_t rka[4];
    #pragma unroll
    for (int q = 0; q < 4; q++) {
        int rk = ks * 4 + q;
        asm("mapa.shared::cluster.u32 %0, %1, %2;" : "=r"(rka[q]) : "r"(dst0), "r"(rk));
    }
    const uint32_t PAR_OFF = 8u * GSTR * 4u;

    const float* w0r = W_s + (hd)      * GSTR + ks * KSOFF;
    const float* w1r = W_s + (32 + hd) * GSTR + ks * KSOFF;
    const float* w2r = W_s + (64 + hd) * GSTR + ks * KSOFF;
    const float* w3r = W_s + (96 + hd) * GSTR + ks * KSOFF;
    const float* hbase = h_loc + b * GSTR + ks * KSOFF;
    const float* xg_rd = xg_s + (b * 4) * XG_STRIDE + hd;   // + g*XG_STRIDE + buf sel

    for (int s = 0; s < 256; s++) {
        int p  = s & 1;
        int wp = p ^ 1;

        // xg for step s is ready (issued 1 step ahead); make visible to all
        asm volatile("cp.async.wait_group 1;");
        __syncthreads();

        // prefetch xg for step s+1 into the other buffer
        if (s < 255) {
            int tn = dir ? (254 - s) : (s + 1);
            size_t toff = (size_t)tn * 64 * 2048;
            uint32_t dbase = xg_sm_base + (uint32_t)(((s + 1) & 1) * XG_BUF * 4);
            asm volatile("cp.async.ca.shared.global [%0], [%1], 4;" ::
                         "r"(dbase + xdst0), "l"(xsrc0 + toff));
            asm volatile("cp.async.ca.shared.global [%0], [%1], 4;" ::
                         "r"(dbase + xdst1), "l"(xsrc1 + toff));
        }
        asm volatile("cp.async.commit_group;");

        // ---- dot products: 4 gates x K/2 for (hd, b) ----
        const float* hr = hbase + p * 8 * GSTR;
        unsigned long long a0 = 0, a1 = 0, a2 = 0, a3 = 0;
        #pragma unroll 4
        for (int k8 = 0; k8 < 16; k8++) {
            ulonglong2 hA = *(const ulonglong2*)(hr + k8 * 8);
            ulonglong2 hB = *(const ulonglong2*)(hr + k8 * 8 + 4);
            ulonglong2 wA, wB;
            wA = *(const ulonglong2*)(w0r + k8 * 8);
            wB = *(const ulonglong2*)(w0r + k8 * 8 + 4);
            FMA2(a0, wA.x, hA.x); FMA2(a0, wA.y, hA.y);
            FMA2(a0, wB.x, hB.x); FMA2(a0, wB.y, hB.y);
            wA = *(const ulonglong2*)(w1r + k8 * 8);
            wB = *(const ulonglong2*)(w1r + k8 * 8 + 4);
            FMA2(a1, wA.x, hA.x); FMA2(a1, wA.y, hA.y);
            FMA2(a1, wB.x, hB.x); FMA2(a1, wB.y, hB.y);
            wA = *(const ulonglong2*)(w2r + k8 * 8);
            wB = *(const ulonglong2*)(w2r + k8 * 8 + 4);
            FMA2(a2, wA.x, hA.x); FMA2(a2, wA.y, hA.y);
            FMA2(a2, wB.x, hB.x); FMA2(a2, wB.y, hB.y);
            wA = *(const ulonglong2*)(w3r + k8 * 8);
            wB = *(const ulonglong2*)(w3r + k8 * 8 + 4);
            FMA2(a3, wA.x, hA.x); FMA2(a3, wA.y, hA.y);
            FMA2(a3, wB.x, hB.x); FMA2(a3, wB.y, hB.y);
        }

        // fold f32x2 halves + cross-ks reduce
        float d0, d1, d2, d3;
        {
            unsigned int lo, hi;
            UNPK2(lo, hi, a0); d0 = __uint_as_float(lo) + __uint_as_float(hi);
            UNPK2(lo, hi, a1); d1 = __uint_as_float(lo) + __uint_as_float(hi);
            UNPK2(lo, hi, a2); d2 = __uint_as_float(lo) + __uint_as_float(hi);
            UNPK2(lo, hi, a3); d3 = __uint_as_float(lo) + __uint_as_float(hi);
            d0 += __shfl_xor_sync(0xFFFFFFFFu, d0, 1);
            d1 += __shfl_xor_sync(0xFFFFFFFFu, d1, 1);
            d2 += __shfl_xor_sync(0xFFFFFFFFu, d2, 1);
            d3 += __shfl_xor_sync(0xFFFFFFFFu, d3, 1);
        }

        // xg preacts from smem buffer (both ks lanes read same -> broadcast)
        const float* xr = xg_rd + (s & 1) * XG_BUF;
        float ig = sigf(d0 + xr[0 * XG_STRIDE]);
        float fg = sigf(d1 + xr[1 * XG_STRIDE]);
        float gg = tanhf(d2 + xr[2 * XG_STRIDE]);
        float og = sigf(d3 + xr[3 * XG_STRIDE]);
        c = fg * c + ig * gg;
        float h = og * tanhf(c);

        // layer output (one lane per (hd,b))
        int t = dir ? (255 - s) : s;
        if (ks == 0)
            y[((size_t)t * 64 + b_g) * 512 + (size_t)dir * 256 + hd_g] = h;

        // push h into 4 of the 8 cluster CTAs' smem (other ks-lane covers rest)
        uint32_t poff = wp ? PAR_OFF : 0u;
        #pragma unroll
        for (int q = 0; q < 4; q++)
            asm volatile("st.shared::cluster.f32 [%0], %1;"
                         :: "r"(rka[q] + poff), "f"(h) : "memory");

        asm volatile("barrier.cluster.arrive.aligned;" ::: "memory");
        asm volatile("barrier.cluster.wait.aligned;"   ::: "memory");
    }
}

// ============================================================
// 4) hidden2tag
// ============================================================
__global__ void __launch_bounds__(256)
feats_kernel(const float* __restrict__ w_out, const float* __restrict__ b_out)
{
    __shared__ float ws[7 * 512];
    __shared__ float bs[7];
    int tid = threadIdx.x;
    for (int i = tid; i < 3584; i += 256) ws[i] = w_out[i];
    if (tid < 7) bs[tid] = b_out[tid];
    __syncthreads();

    int gw   = (blockIdx.x * 256 + tid) >> 5;
    int lane = tid & 31;
    int nw   = gridDim.x * 8;
    for (int m = gw; m < 16384; m += nw) {
        const float4* y4 = (const float4*)(g_y1 + (size_t)m * 512);
        float acc[7] = {0, 0, 0, 0, 0, 0, 0};
        #pragma unroll
        for (int q = 0; q < 4; q++) {
            int k4 = q * 32 + lane;
            float4 yv = y4[k4];
            #pragma unroll
            for (int tg = 0; tg < 7; tg++) {
                float4 wv = *(const float4*)(ws + tg * 512 + k4 * 4);
                acc[tg] += yv.x * wv.x + yv.y * wv.y + yv.z * wv.z + yv.w * wv.w;
            }
        }
        #pragma unroll
        for (int tg = 0; tg < 7; tg++) {
            #pragma unroll
            for (int off = 16; off; off >>= 1)
                acc[tg] += __shfl_xor_sync(0xFFFFFFFFu, acc[tg], off);
        }
        float v = acc[0];
        #pragma unroll
        for (int tg = 1; tg < 7; tg++) if (lane == tg) v = acc[tg];
        if (lane < 7) g_feats[m * 7 + lane] = v + bs[lane];
    }
}

// ============================================================
// 5) Viterbi: 1 CTA, thread = batch; packed backpointers in smem.
//    out = [path as float (B*T)] ++ [score (B)]
// ============================================================
__global__ void __launch_bounds__(64)
viterbi_kernel(const float* __restrict__ trans, float* __restrict__ out)
{
    extern __shared__ unsigned int bp_s[];   // [256][64]
    __shared__ float tr[49];
    int b = threadIdx.x;
    if (b < 49) tr[b] = trans[b];
    __syncthreads();

    float v[7];
    #pragma unroll
    for (int k = 0; k < 7; k++) v[k] = (k == 5) ? 0.0f : NEG_;  // START=5

    for (int t = 0; t < 256; t++) {
        const float* f = g_feats + ((size_t)t * 64 + b) * 7;
        float fv[7];
        #pragma unroll
        for (int k = 0; k < 7; k++) fv[k] = f[k];

        unsigned int word = 0;
        float nv[7];
        #pragma unroll
        for (int nx = 0; nx < 7; nx++) {
            float best = v[0] + tr[nx * 7 + 0];
            int arg = 0;
            #pragma unroll
            for (int pv = 1; pv < 7; pv++) {
                float sc = v[pv] + tr[nx * 7 + pv];
                if (sc > best) { best = sc; arg = pv; }
            }
            nv[nx] = best + fv[nx];
            word |= ((unsigned int)arg) << (3 * nx);
        }
        #pragma unroll
        for (int k = 0; k < 7; k++) v[k] = nv[k];
        bp_s[t * 64 + b] = word;
    }

    float best = v[0] + tr[6 * 7 + 0];
    int last = 0;
    #pragma unroll
    for (int k = 1; k < 7; k++) {
        float sc = v[k] + tr[6 * 7 + k];
        if (sc > best) { best = sc; last = k; }
    }
    out[16384 + b] = best;

    int tag = last;
    out[(size_t)b * 256 + 255] = (float)tag;
    for (int t = 254; t >= 0; t--) {
        unsigned int w = bp_s[(t + 1) * 64 + b];
        tag = (int)((w >> (3 * tag)) & 7u);
        out[(size_t)b * 256 + t] = (float)tag;
    }
}

// ============================================================
// launcher
// ============================================================
extern "C" void kernel_launch(void* const* d_in, const int* in_sizes, int n_in,
                              void* d_out, int out_size)
{
    (void)in_sizes; (void)n_in; (void)out_size;
    const int*   sent  = (const int*)  d_in[0];
    const float* emb   = (const float*)d_in[1];
    const float* w_ih  = (const float*)d_in[2];
    const float* w_hh  = (const float*)d_in[3];
    const float* b_ih  = (const float*)d_in[4];
    const float* b_hh  = (const float*)d_in[5];
    const float* w_out = (const float*)d_in[6];
    const float* b_out = (const float*)d_in[7];
    const float* trans = (const float*)d_in[8];
    const float* h0    = (const float*)d_in[9];
    const float* c0    = (const float*)d_in[10];
    float* out = (float*)d_out;

    cudaFuncSetAttribute(lstm_kernel, cudaFuncAttributeMaxDynamicSharedMemorySize,
                         LSTM_SMEM_BYTES);
    cudaFuncSetAttribute(viterbi_kernel, cudaFuncAttributeMaxDynamicSharedMemorySize,
                         VIT_SMEM_BYTES);

    embed_kernel<<<256, 256>>>(sent, emb);
    for (int l = 0; l < 2; l++) {
        gemm_kernel<<<dim3(16, 128), 256>>>(w_ih + (size_t)l * 2048 * 512,
                                            b_ih + l * 2048,
                                            b_hh + l * 2048, l);
        lstm_kernel<<<128, 512, LSTM_SMEM_BYTES>>>(w_hh + (size_t)l * 2 * 1024 * 256,
                                                   h0, c0, l);
    }
    feats_kernel<<<256, 256>>>(w_out, b_out);
    viterbi_kernel<<<1, 64, VIT_SMEM_BYTES>>>(trans, out);
}

// round 12
// speedup vs baseline: 1.1457x; 1.1457x over previous
#include <cuda_runtime.h>
#include <cuda_bf16.h>
#include <cstdint>

// Problem: T=256, B=64, E=512, H=512, HD=256, L=2, K=7
#define NEG_ -10000.0f

// packed f32x2 helpers (sm_103a)
#define FMA2(d, a, b) asm("fma.rn.f32x2 %0, %1, %2, %0;" : "+l"(d) : "l"(a), "l"(b))
#define PACK2(out, v) asm("mov.b64 %0, {%1, %1};" : "=l"(out) : "r"(__float_as_uint(v)))
#define UNPK2(lo, hi, in) asm("mov.b64 {%0, %1}, %2;" : "=r"(lo), "=r"(hi) : "l"(in))

// ---------------- device scratch (no cudaMalloc allowed) ----------------
__device__ float g_x [16384*512];   // embedded input (layer0 GEMM A)
__device__ float g_y0[16384*512];   // layer0 hidden output [m][dir*256+hd]
__device__ float g_y1[16384*512];   // layer1 hidden output
__device__ float g_xg[16384*2048];  // input-gate preacts [m][dir*1024 + gate*256 + hd]
__device__ float g_feats[16384*7];

// LSTM smem layout: W rows 128 x 276 floats, h rows 16 x 276 floats, then mbarrier.
#define GSTR  276
#define KSOFF 144
#define W_FLOATS (128*GSTR)
#define H_FLOATS (16*GSTR)
#define MBAR_BYTE_OFF ((W_FLOATS + H_FLOATS) * 4)     /* 158976, 8B-aligned */
#define LSTM_SMEM_BYTES (MBAR_BYTE_OFF + 16)
#define VIT_SMEM_BYTES  (256*64*4)                    /* 65536  */

// ============================================================
// 1) Embedding gather
// ============================================================
__global__ void __launch_bounds__(256) embed_kernel(const int* __restrict__ sent,
                                                    const float* __restrict__ emb)
{
    int gw   = (blockIdx.x * 256 + threadIdx.x) >> 5;
    int lane = threadIdx.x & 31;
    int nw   = gridDim.x * 8;
    for (int row = gw; row < 16384; row += nw) {
        int tok = sent[row];
        const float4* s = (const float4*)(emb + (size_t)tok * 512);
        float4*       d = (float4*)(g_x + (size_t)row * 512);
        #pragma unroll
        for (int i = 0; i < 4; i++) d[lane + i * 32] = s[lane + i * 32];
    }
}

// ============================================================
// 2) GEMM: g_xg[m][n] = A[m][:] . W[n][:] + b1[n] + b2[n]
//    128x128 tile, BK=8, 256 threads, 8x8 microtile via f32x2 FMA,
//    double-buffered smem (one __syncthreads per k-tile).
// ============================================================
__global__ void __launch_bounds__(256, 2)
gemm_kernel(const float* __restrict__ W, const float* __restrict__ b1,
            const float* __restrict__ b2, int layer)
{
    const float* A = layer ? g_y0 : g_x;
    __shared__ __align__(16) float As[2][8][132];
    __shared__ __align__(16) float Bs[2][8][132];

    int tid  = threadIdx.x;
    int m0   = blockIdx.y * 128;
    int n0   = blockIdx.x * 128;
    int lrow = tid >> 1;            // 0..127
    int kc   = (tid & 1) * 4;       // 0 or 4
    const float* Ap = A + (size_t)(m0 + lrow) * 512 + kc;
    const float* Wp = W + (size_t)(n0 + lrow) * 512 + kc;
    int tr = tid >> 4;              // 0..15
    int tc = tid & 15;              // 0..15

    unsigned long long acc2[8][4];
    #pragma unroll
    for (int i = 0; i < 8; i++)
        #pragma unroll
        for (int j = 0; j < 4; j++) acc2[i][j] = 0ull;

    {
        float4 pa = *(const float4*)Ap;
        float4 pb = *(const float4*)Wp;
        As[0][kc + 0][lrow] = pa.x; As[0][kc + 1][lrow] = pa.y;
        As[0][kc + 2][lrow] = pa.z; As[0][kc + 3][lrow] = pa.w;
        Bs[0][kc + 0][lrow] = pb.x; Bs[0][kc + 1][lrow] = pb.y;
        Bs[0][kc + 2][lrow] = pb.z; Bs[0][kc + 3][lrow] = pb.w;
    }
    __syncthreads();

    for (int kt = 0; kt < 64; kt++) {
        int cur = kt & 1;
        float4 na, nb;
        if (kt < 63) {
            na = *(const float4*)(Ap + (kt + 1) * 8);
            nb = *(const float4*)(Wp + (kt + 1) * 8);
        }
        #pragma unroll
        for (int kk = 0; kk < 8; kk++) {
            float4 alo = *(const float4*)&As[cur][kk][tr * 4];
            float4 ahi = *(const float4*)&As[cur][kk][64 + tr * 4];
            ulonglong2 bl = *(const ulonglong2*)&Bs[cur][kk][tc * 4];
            ulonglong2 bh = *(const ulonglong2*)&Bs[cur][kk][64 + tc * 4];
            float av[8] = {alo.x, alo.y, alo.z, alo.w, ahi.x, ahi.y, ahi.z, ahi.w};
            #pragma unroll
            for (int i = 0; i < 8; i++) {
                unsigned long long a2;
                PACK2(a2, av[i]);
                FMA2(acc2[i][0], a2, bl.x);
                FMA2(acc2[i][1], a2, bl.y);
                FMA2(acc2[i][2], a2, bh.x);
                FMA2(acc2[i][3], a2, bh.y);
            }
        }
        if (kt < 63) {
            int nxt = cur ^ 1;
            As[nxt][kc + 0][lrow] = na.x; As[nxt][kc + 1][lrow] = na.y;
            As[nxt][kc + 2][lrow] = na.z; As[nxt][kc + 3][lrow] = na.w;
            Bs[nxt][kc + 0][lrow] = nb.x; Bs[nxt][kc + 1][lrow] = nb.y;
            Bs[nxt][kc + 2][lrow] = nb.z; Bs[nxt][kc + 3][lrow] = nb.w;
            __syncthreads();
        }
    }

    #pragma unroll
    for (int i = 0; i < 8; i++) {
        int r = m0 + ((i < 4) ? (tr * 4 + i) : (64 + tr * 4 + i - 4));
        #pragma unroll
        for (int jh = 0; jh < 2; jh++) {
            int cb = n0 + jh * 64 + tc * 4;
            unsigned int u0, u1, u2, u3;
            UNPK2(u0, u1, acc2[i][jh * 2 + 0]);
            UNPK2(u2, u3, acc2[i][jh * 2 + 1]);
            float4 o;
            o.x = __uint_as_float(u0) + b1[cb + 0] + b2[cb + 0];
            o.y = __uint_as_float(u1) + b1[cb + 1] + b2[cb + 1];
            o.z = __uint_as_float(u2) + b1[cb + 2] + b2[cb + 2];
            o.w = __uint_as_float(u3) + b1[cb + 3] + b2[cb + 3];
            *(float4*)(g_xg + (size_t)r * 2048 + cb) = o;
        }
    }
}

// ============================================================
// 3) LSTM recurrence (one layer, both dirs).
//    128 CTAs = 16 clusters of 8; cluster = (dir, 8-batch chunk);
//    CTA rank r owns hd in [r*32, r*32+32).
//    Sync: NO per-step cluster barrier. Each CTA owns a local
//    tx-mbarrier; producers deliver h via
//    st.async.shared::cluster.mbarrier::complete_tx::bytes into all
//    8 CTAs' smem; each CTA arms expect_tx(8192)/step and spins
//    try_wait.parity.acquire.cluster. Double-buffer reuse is safe:
//    phase-k completion implies all ranks finished reading buf k&1.
// ============================================================
__device__ __forceinline__ float sigf(float x) { return 1.0f / (1.0f + __expf(-x)); }

__global__ void __cluster_dims__(8, 1, 1) __launch_bounds__(256, 1)
lstm_kernel(const float* __restrict__ w_hh,   // layer base: [2][1024][256]
            const float* __restrict__ h0,     // [4][64][256]
            const float* __restrict__ c0,
            int layer)
{
    extern __shared__ float smem[];
    float* W_s   = smem;                 // 128 rows x GSTR
    float* h_loc = smem + W_FLOATS;      // 16 rows (2 parity x 8 b) x GSTR

    float* y = layer ? g_y1 : g_y0;

    int bx  = blockIdx.x;
    int cid = bx >> 3;                   // 0..15
    int r   = bx & 7;                    // hd-chunk rank
    int dir = cid & 1;
    int bc  = cid >> 1;                  // batch chunk 0..7
    int tid = threadIdx.x;
    int hd  = tid >> 3;                  // 0..31
    int bp  = (tid >> 1) & 3;            // batch pair 0..3
    int ks  = tid & 1;                   // K-half
    int hd_g = r * 32 + hd;
    int b_ep = bp * 2 + ks;              // epilogue batch within chunk
    int b_g  = bc * 8 + b_ep;

    // ---- load W_hh slice into split-row layout ----
    const float* Wd = w_hh + (size_t)dir * 1024 * 256;
    for (int i = tid; i < 128 * 64; i += 256) {
        int row = i >> 6, q = i & 63;
        int grow = (row >> 5) * 256 + r * 32 + (row & 31);
        float4 v = *(const float4*)(Wd + (size_t)grow * 256 + q * 4);
        int col = (q < 32) ? q * 4 : KSOFF + (q - 32) * 4;
        *(float4*)(W_s + row * GSTR + col) = v;
    }
    // ---- initial h (parity 0) ----
    const float* h0d = h0 + ((size_t)(2 * layer + dir) * 64 + bc * 8) * 256;
    for (int i = tid; i < 512; i += 256) {
        int row = i >> 6, q = i & 63;
        float4 v = *(const float4*)(h0d + row * 256 + q * 4);
        int col = (q < 32) ? q * 4 : KSOFF + (q - 32) * 4;
        *(float4*)(h_loc + row * GSTR + col) = v;
    }
    float c = c0[((size_t)(2 * layer + dir) * 64 + b_g) * 256 + hd_g];

    // local mbarrier init (count = 1; completion driven by tx bytes)
    uint32_t smem_u32 = (uint32_t)__cvta_generic_to_shared(smem);
    uint32_t mbar_l   = smem_u32 + MBAR_BYTE_OFF;
    if (tid == 0)
        asm volatile("mbarrier.init.shared.b64 [%0], 1;" :: "r"(mbar_l) : "memory");
    __syncthreads();
    // one-time cluster sync: all mbarriers initialized before any st.async
    asm volatile("barrier.cluster.arrive.aligned;" ::: "memory");
    asm volatile("barrier.cluster.wait.aligned;"   ::: "memory");

    // precompute remote addresses (data slot + mbarrier) for all 8 ranks
    uint32_t h_base = smem_u32 + (uint32_t)(W_FLOATS * 4);
    int col_hd = (hd_g < 128) ? hd_g : KSOFF + (hd_g - 128);
    uint32_t dst0 = h_base + (uint32_t)((b_ep * GSTR + col_hd) * 4);
    uint32_t rka[8], rmb[8];
    #pragma unroll
    for (int rk = 0; rk < 8; rk++) {
        asm("mapa.shared::cluster.u32 %0, %1, %2;" : "=r"(rka[rk]) : "r"(dst0),   "r"(rk));
        asm("mapa.shared::cluster.u32 %0, %1, %2;" : "=r"(rmb[rk]) : "r"(mbar_l), "r"(rk));
    }
    const uint32_t PAR_OFF = 8u * GSTR * 4u;

    const float* w0r = W_s + (hd)      * GSTR + ks * KSOFF;
    const float* w1r = W_s + (32 + hd) * GSTR + ks * KSOFF;
    const float* w2r = W_s + (64 + hd) * GSTR + ks * KSOFF;
    const float* w3r = W_s + (96 + hd) * GSTR + ks * KSOFF;
    const float* hb  = h_loc + bp * 2 * GSTR + ks * KSOFF;

    for (int s = 0; s < 256; s++) {
        int t  = dir ? (255 - s) : s;
        int p  = s & 1;
        int wp = p ^ 1;

        // arm this step's phase: 1 arrive + 8192 tx bytes expected
        if (tid == 0 && s < 255)
            asm volatile("mbarrier.arrive.expect_tx.shared.b64 _, [%0], 8192;"
                         :: "r"(mbar_l) : "memory");

        // prefetch input-gate preacts for epilogue batch
        size_t xb = ((size_t)t * 64 + b_g) * 2048 + (size_t)dir * 1024 + hd_g;
        float xg0 = g_xg[xb];
        float xg1 = g_xg[xb + 256];
        float xg2 = g_xg[xb + 512];
        float xg3 = g_xg[xb + 768];

        const float* hr0 = hb + p * 8 * GSTR;        // batch bp*2
        const float* hr1 = hr0 + GSTR;               // batch bp*2+1

        unsigned long long a00 = 0, a01 = 0, a10 = 0, a11 = 0;
        unsigned long long a20 = 0, a21 = 0, a30 = 0, a31 = 0;
        #pragma unroll 8
        for (int k4 = 0; k4 < 32; k4++) {
            ulonglong2 h0v = *(const ulonglong2*)(hr0 + k4 * 4);
            ulonglong2 h1v = *(const ulonglong2*)(hr1 + k4 * 4);
            ulonglong2 w0v = *(const ulonglong2*)(w0r + k4 * 4);
            ulonglong2 w1v = *(const ulonglong2*)(w1r + k4 * 4);
            ulonglong2 w2v = *(const ulonglong2*)(w2r + k4 * 4);
            ulonglong2 w3v = *(const ulonglong2*)(w3r + k4 * 4);
            FMA2(a00, w0v.x, h0v.x); FMA2(a00, w0v.y, h0v.y);
            FMA2(a01, w0v.x, h1v.x); FMA2(a01, w0v.y, h1v.y);
            FMA2(a10, w1v.x, h0v.x); FMA2(a10, w1v.y, h0v.y);
            FMA2(a11, w1v.x, h1v.x); FMA2(a11, w1v.y, h1v.y);
            FMA2(a20, w2v.x, h0v.x); FMA2(a20, w2v.y, h0v.y);
            FMA2(a21, w2v.x, h1v.x); FMA2(a21, w2v.y, h1v.y);
            FMA2(a30, w3v.x, h0v.x); FMA2(a30, w3v.y, h0v.y);
            FMA2(a31, w3v.x, h1v.x); FMA2(a31, w3v.y, h1v.y);
        }

        // fold f32x2 halves, then K-half reduce with partner lane (ks^1)
        float d0, d1, d2, d3;
        {
            unsigned int lo, hi; float v0, v1;
            UNPK2(lo, hi, a00); v0 = __uint_as_float(lo) + __uint_as_float(hi);
            UNPK2(lo, hi, a01); v1 = __uint_as_float(lo) + __uint_as_float(hi);
            v0 += __shfl_xor_sync(0xFFFFFFFFu, v0, 1);
            v1 += __shfl_xor_sync(0xFFFFFFFFu, v1, 1);
            d0 = ks ? v1 : v0;
            UNPK2(lo, hi, a10); v0 = __uint_as_float(lo) + __uint_as_float(hi);
            UNPK2(lo, hi, a11); v1 = __uint_as_float(lo) + __uint_as_float(hi);
            v0 += __shfl_xor_sync(0xFFFFFFFFu, v0, 1);
            v1 += __shfl_xor_sync(0xFFFFFFFFu, v1, 1);
            d1 = ks ? v1 : v0;
            UNPK2(lo, hi, a20); v0 = __uint_as_float(lo) + __uint_as_float(hi);
            UNPK2(lo, hi, a21); v1 = __uint_as_float(lo) + __uint_as_float(hi);
            v0 += __shfl_xor_sync(0xFFFFFFFFu, v0, 1);
            v1 += __shfl_xor_sync(0xFFFFFFFFu, v1, 1);
            d2 = ks ? v1 : v0;
            UNPK2(lo, hi, a30); v0 = __uint_as_float(lo) + __uint_as_float(hi);
            UNPK2(lo, hi, a31); v1 = __uint_as_float(lo) + __uint_as_float(hi);
            v0 += __shfl_xor_sync(0xFFFFFFFFu, v0, 1);
            v1 += __shfl_xor_sync(0xFFFFFFFFu, v1, 1);
            d3 = ks ? v1 : v0;
        }

        float ig = sigf(d0 + xg0);
        float fg = sigf(d1 + xg1);
        float gg = tanhf(d2 + xg2);
        float og = sigf(d3 + xg3);
        c = fg * c + ig * gg;
        float h = og * tanhf(c);

        // layer output (fire-and-forget; nothing forces a drain now)
        y[((size_t)t * 64 + b_g) * 512 + (size_t)dir * 256 + hd_g] = h;

        if (s < 255) {
            // deliver h to all 8 cluster CTAs; each store signals the
            // destination CTA's mbarrier with 4 tx bytes on completion
            uint32_t poff = wp ? PAR_OFF : 0u;
            unsigned int hv = __float_as_uint(h);
            #pragma unroll
            for (int rk = 0; rk < 8; rk++)
                asm volatile(
                    "st.async.weak.shared::cluster.mbarrier::complete_tx::bytes.b32 [%0], %1, [%2];"
                    :: "r"(rka[rk] + poff), "r"(hv), "r"(rmb[rk]) : "memory");

            // wait for this step's phase (all 8KB delivered), acquire cluster
            unsigned int par = (unsigned int)(s & 1);
            asm volatile(
                "{\n\t"
                ".reg .pred P;\n\t"
                "WAIT_%=:\n\t"
                "mbarrier.try_wait.parity.acquire.cluster.shared::cta.b64 P, [%0], %1, 0x989680;\n\t"
                "@!P bra WAIT_%=;\n\t"
                "}"
                :: "r"(mbar_l), "r"(par) : "memory");
        }
    }
}

// ============================================================
// 4) hidden2tag
// ============================================================
__global__ void __launch_bounds__(256)
feats_kernel(const float* __restrict__ w_out, const float* __restrict__ b_out)
{
    __shared__ float ws[7 * 512];
    __shared__ float bs[7];
    int tid = threadIdx.x;
    for (int i = tid; i < 3584; i += 256) ws[i] = w_out[i];
    if (tid < 7) bs[tid] = b_out[tid];
    __syncthreads();

    int gw   = (blockIdx.x * 256 + tid) >> 5;
    int lane = tid & 31;
    int nw   = gridDim.x * 8;
    for (int m = gw; m < 16384; m += nw) {
        const float4* y4 = (const float4*)(g_y1 + (size_t)m * 512);
        float acc[7] = {0, 0, 0, 0, 0, 0, 0};
        #pragma unroll
        for (int q = 0; q < 4; q++) {
            int k4 = q * 32 + lane;
            float4 yv = y4[k4];
            #pragma unroll
            for (int tg = 0; tg < 7; tg++) {
                float4 wv = *(const float4*)(ws + tg * 512 + k4 * 4);
                acc[tg] += yv.x * wv.x + yv.y * wv.y + yv.z * wv.z + yv.w * wv.w;
            }
        }
        #pragma unroll
        for (int tg = 0; tg < 7; tg++) {
            #pragma unroll
            for (int off = 16; off; off >>= 1)
                acc[tg] += __shfl_xor_sync(0xFFFFFFFFu, acc[tg], off);
        }
        float v = acc[0];
        #pragma unroll
        for (int tg = 1; tg < 7; tg++) if (lane == tg) v = acc[tg];
        if (lane < 7) g_feats[m * 7 + lane] = v + bs[lane];
    }
}

// ============================================================
// 5) Viterbi: 1 CTA, thread = batch; packed backpointers in smem.
//    out = [path as float (B*T)] ++ [score (B)]
// ============================================================
__global__ void __launch_bounds__(64)
viterbi_kernel(const float* __restrict__ trans, float* __restrict__ out)
{
    extern __shared__ unsigned int bp_s[];   // [256][64]
    __shared__ float tr[49];
    int b = threadIdx.x;
    if (b < 49) tr[b] = trans[b];
    __syncthreads();

    float v[7];
    #pragma unroll
    for (int k = 0; k < 7; k++) v[k] = (k == 5) ? 0.0f : NEG_;  // START=5

    for (int t = 0; t < 256; t++) {
        const float* f = g_feats + ((size_t)t * 64 + b) * 7;
        float fv[7];
        #pragma unroll
        for (int k = 0; k < 7; k++) fv[k] = f[k];

        unsigned int word = 0;
        float nv[7];
        #pragma unroll
        for (int nx = 0; nx < 7; nx++) {
            float best = v[0] + tr[nx * 7 + 0];
            int arg = 0;
            #pragma unroll
            for (int pv = 1; pv < 7; pv++) {
                float sc = v[pv] + tr[nx * 7 + pv];
                if (sc > best) { best = sc; arg = pv; }
            }
            nv[nx] = best + fv[nx];
            word |= ((unsigned int)arg) << (3 * nx);
        }
        #pragma unroll
        for (int k = 0; k < 7; k++) v[k] = nv[k];
        bp_s[t * 64 + b] = word;
    }

    float best = v[0] + tr[6 * 7 + 0];
    int last = 0;
    #pragma unroll
    for (int k = 1; k < 7; k++) {
        float sc = v[k] + tr[6 * 7 + k];
        if (sc > best) { best = sc; last = k; }
    }
    out[16384 + b] = best;

    int tag = last;
    out[(size_t)b * 256 + 255] = (float)tag;
    for (int t = 254; t >= 0; t--) {
        unsigned int w = bp_s[(t + 1) * 64 + b];
        tag = (int)((w >> (3 * tag)) & 7u);
        out[(size_t)b * 256 + t] = (float)tag;
    }
}

// ============================================================
// launcher
// ============================================================
extern "C" void kernel_launch(void* const* d_in, const int* in_sizes, int n_in,
                              void* d_out, int out_size)
{
    (void)in_sizes; (void)n_in; (void)out_size;
    const int*   sent  = (const int*)  d_in[0];
    const float* emb   = (const float*)d_in[1];
    const float* w_ih  = (const float*)d_in[2];
    const float* w_hh  = (const float*)d_in[3];
    const float* b_ih  = (const float*)d_in[4];
    const float* b_hh  = (const float*)d_in[5];
    const float* w_out = (const float*)d_in[6];
    const float* b_out = (const float*)d_in[7];
    const float* trans = (const float*)d_in[8];
    const float* h0    = (const float*)d_in[9];
    const float* c0    = (const float*)d_in[10];
    float* out = (float*)d_out;

    cudaFuncSetAttribute(lstm_kernel, cudaFuncAttributeMaxDynamicSharedMemorySize,
                         LSTM_SMEM_BYTES);
    cudaFuncSetAttribute(viterbi_kernel, cudaFuncAttributeMaxDynamicSharedMemorySize,
                         VIT_SMEM_BYTES);

    embed_kernel<<<256, 256>>>(sent, emb);
    for (int l = 0; l < 2; l++) {
        gemm_kernel<<<dim3(16, 128), 256>>>(w_ih + (size_t)l * 2048 * 512,
                                            b_ih + l * 2048,
                                            b_hh + l * 2048, l);
        lstm_kernel<<<128, 256, LSTM_SMEM_BYTES>>>(w_hh + (size_t)l * 2 * 1024 * 256,
                                                   h0, c0, l);
    }
    feats_kernel<<<256, 256>>>(w_out, b_out);
    viterbi_kernel<<<1, 64, VIT_SMEM_BYTES>>>(trans, out);
}